// round 14
// baseline (speedup 1.0000x reference)
#include <cuda_runtime.h>

// ---------------------------------------------------------------------------
// ActorGCN: 2-layer GCN + two 105-way heads + gumbel softmax
// N=100000 nodes, E=1600000 edges, H=64, F_IN=14, heads 105+105
// Layer 1 uses (A@X)@W1; the 15x64 transform is fused into agg16's epilogue.
// Heads GEMM stages logits in smem, then a coalesced warp-per-row softmax
// phase handles gumbel+softmax (all global traffic lane-contiguous).
// RULES learned: (1) no global-loops in grid-1 kernels (issue throttle);
// (2) GEMM-microtile column layouts must never touch global memory.
// ---------------------------------------------------------------------------

#define NN 100000
#define EE 1600000

typedef unsigned long long ull;

__device__ __forceinline__ ull pk2(float lo, float hi) {
    ull r; asm("mov.b64 %0, {%1, %2};" : "=l"(r) : "f"(lo), "f"(hi)); return r;
}
__device__ __forceinline__ void upk2(ull v, float& lo, float& hi) {
    asm("mov.b64 {%0, %1}, %2;" : "=f"(lo), "=f"(hi) : "l"(v));
}
__device__ __forceinline__ ull fma2(ull a, ull b, ull c) {
    ull d; asm("fma.rn.f32x2 %0, %1, %2, %3;" : "=l"(d) : "l"(a), "l"(b), "l"(c)); return d;
}

__device__ float g_bufA[NN * 64];
__device__ float g_bufB[NN * 64];
__device__ float g_x16[NN * 16];
__device__ int   g_ecnt[NN];
__device__ float g_dinv[NN];
__device__ float g_stem[NN];
__device__ int   g_off[NN + 1];
__device__ int   g_cur[NN];
__device__ int2  g_edge[EE];      // .x = src, .y = float bits of dinv[src]
__device__ int   g_csum[1024];
__device__ int   g_is64;

__device__ __forceinline__ int idx_at(const void* p, long long i) {
    return g_is64 ? (int)((const long long*)p)[i] : ((const int*)p)[i];
}

// init counters/stem; block 0 also probes index dtype (int64 vs int32).
__global__ void k_init(const int* __restrict__ ei32, int n) {
    int i = blockIdx.x * blockDim.x + threadIdx.x;
    if (i < n) { g_ecnt[i] = 0; g_stem[i] = 0.f; }
    if (blockIdx.x == 0) {
        __shared__ int nonzero;
        if (threadIdx.x == 0) nonzero = 0;
        __syncthreads();
        for (int k = threadIdx.x; k < 1024; k += blockDim.x) {
            if (ei32[2 * k + 1] != 0) nonzero = 1;
        }
        __syncthreads();
        if (threadIdx.x == 0) g_is64 = nonzero ? 0 : 1;
    }
}

// Fused: stem scatter (i < s) + dst histogram (2 edges per thread).
__global__ void k_prep(const void* __restrict__ ei, const void* __restrict__ si,
                       int e, int s) {
    int i = blockIdx.x * blockDim.x + threadIdx.x;
    if (i < s) {
        int v = idx_at(si, i);
        if (v >= 0 && v < NN) g_stem[v] = 1.0f;
    }
    int j = i * 2;
    if (j < e) {
        if (g_is64) {
            const long long* dst = (const long long*)ei + e;
            int d0 = (int)dst[j];
            if (d0 >= 0 && d0 < NN) atomicAdd(&g_ecnt[d0], 1);
            if (j + 1 < e) {
                int d1 = (int)dst[j + 1];
                if (d1 >= 0 && d1 < NN) atomicAdd(&g_ecnt[d1], 1);
            }
        } else {
            const int* dst = (const int*)ei + e;
            int d0 = dst[j];
            if (d0 >= 0 && d0 < NN) atomicAdd(&g_ecnt[d0], 1);
            if (j + 1 < e) {
                int d1 = dst[j + 1];
                if (d1 >= 0 && d1 < NN) atomicAdd(&g_ecnt[d1], 1);
            }
        }
    }
}

// Warp-per-chunk sums: 1024 chunks, coalesced loads + shfl reduce.
__global__ void k_chunksum(int n) {
    int c = blockIdx.x * 8 + (threadIdx.x >> 5);
    int lane = threadIdx.x & 31;
    int ch = (n + 1023) >> 10;
    int beg = min(n, c * ch), end = min(n, beg + ch);
    int sum = 0;
    for (int i = beg + lane; i < end; i += 32) sum += g_ecnt[i];
    #pragma unroll
    for (int off = 16; off; off >>= 1) sum += __shfl_xor_sync(0xffffffffu, sum, off);
    if (lane == 0) g_csum[c] = sum;
}

// Warp-per-chunk offsets. Each CTA redundantly scans the 1024 chunk sums in
// smem (replaces the dedicated grid-1 scan kernel), then writes its 8 chunks.
__global__ void k_offsets(int n, int e) {
    __shared__ int sh[1024];
    __shared__ int sh2[256];
    int tid = threadIdx.x;        // 256 threads
    int v0 = g_csum[tid * 4], v1 = g_csum[tid * 4 + 1];
    int v2 = g_csum[tid * 4 + 2], v3 = g_csum[tid * 4 + 3];
    int l1 = v0 + v1, l2 = l1 + v2, l3 = l2 + v3;
    sh2[tid] = l3;
    __syncthreads();
    for (int off = 1; off < 256; off <<= 1) {
        int add = (tid >= off) ? sh2[tid - off] : 0;
        __syncthreads();
        sh2[tid] += add;
        __syncthreads();
    }
    int pre = sh2[tid] - l3;
    sh[tid * 4]     = pre;
    sh[tid * 4 + 1] = pre + v0;
    sh[tid * 4 + 2] = pre + l1;
    sh[tid * 4 + 3] = pre + l2;
    __syncthreads();

    int c = blockIdx.x * 8 + (tid >> 5);
    int lane = tid & 31;
    int ch = (n + 1023) >> 10;
    int beg = min(n, c * ch), end = min(n, beg + ch);
    int run = sh[c];
    for (int base = beg; base < end; base += 32) {
        int i = base + lane;
        int d = (i < end) ? g_ecnt[i] : 0;
        int incl = d;
        #pragma unroll
        for (int off = 1; off < 32; off <<= 1) {
            int v = __shfl_up_sync(0xffffffffu, incl, off);
            if (lane >= off) incl += v;
        }
        if (i < end) {
            int o = run + incl - d;
            g_off[i] = o;
            g_cur[i] = o;
            g_dinv[i] = rsqrtf((float)(d + 1));   // +1 self-loop
        }
        run += __shfl_sync(0xffffffffu, incl, 31);
    }
    if (blockIdx.x == 0 && threadIdx.x == 0) g_off[n] = e;
}

// Fused: CSR scatter + pack [x|stem|0] into padded 16-float rows.
__global__ void k_scatter(const void* __restrict__ ei, const float* __restrict__ x,
                          int e, int n) {
    int i = blockIdx.x * blockDim.x + threadIdx.x;
    if (i < e) {
        int s = idx_at(ei, i);
        int d = idx_at(ei, (long long)e + i);
        if (s >= 0 && s < NN && d >= 0 && d < NN) {
            int p = atomicAdd(&g_cur[d], 1);
            if (p >= 0 && p < EE)
                g_edge[p] = make_int2(s, __float_as_int(g_dinv[s]));
        }
    }
    if (i < n * 16) {
        int node = i >> 4, f = i & 15;
        float v = 0.f;
        if (f < 14)       v = x[node * 14 + f];
        else if (f == 14) v = g_stem[node];
        g_x16[i] = v;
    }
}

// Fused layer 1: aggregate 16-feat raw input, then 15x64 transform + bias +
// relu + drop, all in one warp per node. Writes h1 -> g_bufB.
__global__ void k_agg16(const float* __restrict__ W1, const float* __restrict__ b1,
                        const float* __restrict__ drop, int n) {
    __shared__ float sW[15 * 64];
    __shared__ int   s_idx[8][32];
    __shared__ float s_w[8][32];
    int wrp = threadIdx.x >> 5, lane = threadIdx.x & 31;
    for (int idx = threadIdx.x; idx < 15 * 64; idx += 256) sW[idx] = W1[idx];
    __syncthreads();
    int node = blockIdx.x * 8 + wrp;
    if (node >= n) return;
    int f = lane & 15, half = lane >> 4;
    const float* __restrict__ in = g_x16;
    float di = g_dinv[node];
    float acc = half ? 0.f : di * in[node * 16 + f];
    int beg = g_off[node], end = g_off[node + 1];
    for (int base = beg; base < end; base += 32) {
        int m = min(32, end - base);
        if (lane < m) {
            int2 v = g_edge[base + lane];
            s_idx[wrp][lane] = v.x;
            s_w[wrp][lane]   = __int_as_float(v.y);
        }
        __syncwarp();
        int j = 0;
        for (; j + 8 <= m; j += 8) {
            int e0 = j + half, e1 = j + 2 + half, e2 = j + 4 + half, e3 = j + 6 + half;
            float v0 = in[s_idx[wrp][e0] * 16 + f];
            float v1 = in[s_idx[wrp][e1] * 16 + f];
            float v2 = in[s_idx[wrp][e2] * 16 + f];
            float v3 = in[s_idx[wrp][e3] * 16 + f];
            acc = fmaf(s_w[wrp][e0], v0, acc);
            acc = fmaf(s_w[wrp][e1], v1, acc);
            acc = fmaf(s_w[wrp][e2], v2, acc);
            acc = fmaf(s_w[wrp][e3], v3, acc);
        }
        for (; j < m; j += 2) {
            int e2 = j + half;
            if (e2 < m)
                acc = fmaf(s_w[wrp][e2], in[s_idx[wrp][e2] * 16 + f], acc);
        }
        __syncwarp();
    }
    acc += __shfl_xor_sync(0xffffffffu, acc, 16);   // all lanes: a16[lane&15] sum
    float a16v = di * acc;
    float h0 = b1[lane], h1 = b1[lane + 32];
    #pragma unroll
    for (int k = 0; k < 15; k++) {
        float ak = __shfl_sync(0xffffffffu, a16v, k);
        h0 = fmaf(ak, sW[k * 64 + lane], h0);
        h1 = fmaf(ak, sW[k * 64 + lane + 32], h1);
    }
    h0 = fmaxf(h0, 0.f) * drop[(size_t)node * 64 + lane];
    h1 = fmaxf(h1, 0.f) * drop[(size_t)node * 64 + lane + 32];
    g_bufB[node * 64 + lane] = h0;
    g_bufB[node * 64 + lane + 32] = h1;
}

// Pure aggregation of h1 (64 feats): bufA[i] = dinv_i*(dinv_i*h1[i] + sum w*h1[src]).
__global__ void k_agg64(int n) {
    __shared__ int   s_idx[8][32];
    __shared__ float s_w[8][32];
    int wrp = threadIdx.x >> 5, lane = threadIdx.x & 31;
    int node = blockIdx.x * 8 + wrp;
    if (node >= n) return;
    const ull* __restrict__ in2 = (const ull*)g_bufB;
    float di = g_dinv[node];
    float sx, sy;
    upk2(in2[node * 32 + lane], sx, sy);
    ull acc = pk2(di * sx, di * sy);
    int beg = g_off[node], end = g_off[node + 1];
    for (int base = beg; base < end; base += 32) {
        int m = min(32, end - base);
        if (lane < m) {
            int2 v = g_edge[base + lane];
            s_idx[wrp][lane] = v.x;
            s_w[wrp][lane]   = __int_as_float(v.y);
        }
        __syncwarp();
        int j = 0;
        for (; j + 8 <= m; j += 8) {
            ull v0 = in2[s_idx[wrp][j    ] * 32 + lane];
            ull v1 = in2[s_idx[wrp][j + 1] * 32 + lane];
            ull v2 = in2[s_idx[wrp][j + 2] * 32 + lane];
            ull v3 = in2[s_idx[wrp][j + 3] * 32 + lane];
            ull v4 = in2[s_idx[wrp][j + 4] * 32 + lane];
            ull v5 = in2[s_idx[wrp][j + 5] * 32 + lane];
            ull v6 = in2[s_idx[wrp][j + 6] * 32 + lane];
            ull v7 = in2[s_idx[wrp][j + 7] * 32 + lane];
            acc = fma2(v0, pk2(s_w[wrp][j    ], s_w[wrp][j    ]), acc);
            acc = fma2(v1, pk2(s_w[wrp][j + 1], s_w[wrp][j + 1]), acc);
            acc = fma2(v2, pk2(s_w[wrp][j + 2], s_w[wrp][j + 2]), acc);
            acc = fma2(v3, pk2(s_w[wrp][j + 3], s_w[wrp][j + 3]), acc);
            acc = fma2(v4, pk2(s_w[wrp][j + 4], s_w[wrp][j + 4]), acc);
            acc = fma2(v5, pk2(s_w[wrp][j + 5], s_w[wrp][j + 5]), acc);
            acc = fma2(v6, pk2(s_w[wrp][j + 6], s_w[wrp][j + 6]), acc);
            acc = fma2(v7, pk2(s_w[wrp][j + 7], s_w[wrp][j + 7]), acc);
        }
        for (; j < m; j++) {
            ull v = in2[s_idx[wrp][j] * 32 + lane];
            float w = s_w[wrp][j];
            acc = fma2(v, pk2(w, w), acc);
        }
        __syncwarp();
    }
    float ax, ay;
    upk2(acc, ax, ay);
    ((float2*)g_bufA)[node * 32 + lane] = make_float2(di * ax, di * ay);
}

// h2 = relu(bufA @ W2 + b2) * drop2 -> bufB. 64 threads, BM=64, 8x8, f32x2.
__global__ void k_gemm64(const float* __restrict__ W, const float* __restrict__ b2,
                         const float* __restrict__ drop, int n) {
    __shared__ float Ash[64 * 65];
    __shared__ float Wsh[64 * 64];
    __shared__ float bsh[64];
    int tid = threadIdx.x;        // 64 threads
    int base = blockIdx.x * 64;
    for (int idx = tid; idx < 4096; idx += 64) Wsh[idx] = W[idx];
    bsh[tid] = b2[tid];
    for (int idx = tid; idx < 4096; idx += 64) {
        int nl = idx >> 6, k = idx & 63;
        int node = base + nl;
        Ash[nl * 65 + k] = (node < n) ? g_bufA[node * 64 + k] : 0.f;
    }
    __syncthreads();
    int tx = tid & 7, ty = tid >> 3;
    ull acc[8][4];
    #pragma unroll
    for (int r = 0; r < 8; r++)
        #pragma unroll
        for (int c = 0; c < 4; c++) acc[r][c] = 0ull;
    #pragma unroll 4
    for (int k = 0; k < 64; k++) {
        const ull* wrow = (const ull*)&Wsh[k * 64 + tx * 8];
        ull w0 = wrow[0], w1 = wrow[1], w2 = wrow[2], w3 = wrow[3];
        #pragma unroll
        for (int r = 0; r < 8; r++) {
            float a = Ash[(ty * 8 + r) * 65 + k];
            ull a2 = pk2(a, a);
            acc[r][0] = fma2(a2, w0, acc[r][0]);
            acc[r][1] = fma2(a2, w1, acc[r][1]);
            acc[r][2] = fma2(a2, w2, acc[r][2]);
            acc[r][3] = fma2(a2, w3, acc[r][3]);
        }
    }
    #pragma unroll
    for (int r = 0; r < 8; r++) {
        int node = base + ty * 8 + r;
        if (node < n) {
            #pragma unroll
            for (int c2 = 0; c2 < 4; c2++) {
                float p0, p1;
                upk2(acc[r][c2], p0, p1);
                int col0 = tx * 8 + c2 * 2;
                float2 dv = ((const float2*)drop)[(size_t)node * 32 + tx * 4 + c2];
                float o0 = fmaxf(p0 + bsh[col0], 0.f) * dv.x;
                float o1 = fmaxf(p1 + bsh[col0 + 1], 0.f) * dv.y;
                ((float2*)g_bufB)[node * 32 + tx * 4 + c2] = make_float2(o0, o1);
            }
        }
    }
}

// Heads GEMM + coalesced fused softmax. BM=64 nodes x 112 cols (105 live),
// one head per blockIdx.y. 128 threads; threads <112 run the GEMM (tx/ty
// microtile), logits staged in smem (reusing Wsh), then 4 warps do
// warp-per-row softmax with ALL global traffic lane-contiguous.
__global__ void k_heads(const float* __restrict__ Wb, const float* __restrict__ bbv,
                        const float* __restrict__ Wst, const float* __restrict__ bsv,
                        const float* __restrict__ gbv, const float* __restrict__ gsv,
                        float* __restrict__ outB, float* __restrict__ outS,
                        float* __restrict__ selB, float* __restrict__ selS, int n) {
    __shared__ float Ash[64 * 65];
    __shared__ float Wsh[64 * 112];   // W during GEMM; logits after
    __shared__ float bias_s[112];
    int tid = threadIdx.x;            // 128 threads
    int base = blockIdx.x * 64;
    const float* __restrict__ W   = blockIdx.y ? Wst : Wb;
    const float* __restrict__ bv  = blockIdx.y ? bsv : bbv;
    const float* __restrict__ gum = blockIdx.y ? gsv : gbv;
    float* __restrict__ out       = blockIdx.y ? outS : outB;
    float* __restrict__ sel       = blockIdx.y ? selS : selB;

    if (tid < 112) {
        bias_s[tid] = (tid < 105) ? bv[tid] : 0.f;
        int col = tid;
        for (int k = 0; k < 64; k++)
            Wsh[k * 112 + col] = (col < 105) ? W[k * 105 + col] : 0.f;
    }
    for (int idx = tid; idx < 4096; idx += 128) {
        int nl = idx >> 6, k = idx & 63;
        int node = base + nl;
        Ash[nl * 65 + k] = (node < n) ? g_bufB[node * 64 + k] : 0.f;
    }
    __syncthreads();

    bool compute = tid < 112;
    int tx = tid % 14, ty = tid / 14;
    ull acc[8][4];
    #pragma unroll
    for (int r = 0; r < 8; r++)
        #pragma unroll
        for (int c = 0; c < 4; c++) acc[r][c] = 0ull;
    if (compute) {
        #pragma unroll 2
        for (int k = 0; k < 64; k++) {
            const ull* wrow = (const ull*)&Wsh[k * 112 + tx * 8];
            ull w0 = wrow[0], w1 = wrow[1], w2 = wrow[2], w3 = wrow[3];
            #pragma unroll
            for (int r = 0; r < 8; r++) {
                float a = Ash[(ty * 8 + r) * 65 + k];
                ull a2 = pk2(a, a);
                acc[r][0] = fma2(a2, w0, acc[r][0]);
                acc[r][1] = fma2(a2, w1, acc[r][1]);
                acc[r][2] = fma2(a2, w2, acc[r][2]);
                acc[r][3] = fma2(a2, w3, acc[r][3]);
            }
        }
    }
    __syncthreads();   // all Wsh reads done -> safe to overwrite with logits
    if (compute) {
        #pragma unroll
        for (int r = 0; r < 8; r++) {
            int row = ty * 8 + r;
            #pragma unroll
            for (int c2 = 0; c2 < 4; c2++) {
                float p0, p1;
                upk2(acc[r][c2], p0, p1);
                int col0 = tx * 8 + c2 * 2;
                Wsh[row * 112 + col0]     = p0 + bias_s[col0];
                Wsh[row * 112 + col0 + 1] = p1 + bias_s[col0 + 1];
            }
        }
    }
    __syncthreads();

    // Softmax phase: 4 warps x 16 rows, all global accesses coalesced.
    int wrp = tid >> 5, lane = tid & 31;
    for (int rr = 0; rr < 16; rr++) {
        int row = wrp * 16 + rr;
        int node = base + row;
        if (node >= n) break;
        const float* L = &Wsh[row * 112];
        size_t o = (size_t)node * 105;
        float l0 = L[lane], l1 = L[lane + 32], l2 = L[lane + 64];
        float l3 = (lane < 9) ? L[lane + 96] : 0.f;
        float z0 = l0 + gum[o + lane];
        float z1 = l1 + gum[o + lane + 32];
        float z2 = l2 + gum[o + lane + 64];
        float z3 = (lane < 9) ? (l3 + gum[o + lane + 96]) : -1e30f;
        float m = fmaxf(fmaxf(z0, z1), fmaxf(z2, z3));
        #pragma unroll
        for (int off = 16; off; off >>= 1) m = fmaxf(m, __shfl_xor_sync(0xffffffffu, m, off));
        float e0 = __expf(z0 - m), e1 = __expf(z1 - m), e2 = __expf(z2 - m);
        float e3 = (lane < 9) ? __expf(z3 - m) : 0.f;
        float s = e0 + e1 + e2 + e3;
        #pragma unroll
        for (int off = 16; off; off >>= 1) s += __shfl_xor_sync(0xffffffffu, s, off);
        float inv = 1.0f / s;
        out[o + lane]      = l0;
        out[o + lane + 32] = l1;
        out[o + lane + 64] = l2;
        if (lane < 9) out[o + lane + 96] = l3;
        sel[o + lane]      = e0 * inv;
        sel[o + lane + 32] = e1 * inv;
        sel[o + lane + 64] = e2 * inv;
        if (lane < 9) sel[o + lane + 96] = e3 * inv;
    }
}

extern "C" void kernel_launch(void* const* d_in, const int* in_sizes, int n_in,
                              void* d_out, int out_size) {
    const float* x   = (const float*)d_in[0];
    const float* W1  = (const float*)d_in[1];
    const float* b1  = (const float*)d_in[2];
    const float* W2  = (const float*)d_in[3];
    const float* b2  = (const float*)d_in[4];
    const float* Wb  = (const float*)d_in[5];
    const float* bb  = (const float*)d_in[6];
    const float* Ws  = (const float*)d_in[7];
    const float* bs  = (const float*)d_in[8];
    const float* dr1 = (const float*)d_in[9];
    const float* dr2 = (const float*)d_in[10];
    const float* gb  = (const float*)d_in[11];
    const float* gs  = (const float*)d_in[12];
    const void*  ei  = d_in[13];
    const void*  si  = d_in[14];

    int n = in_sizes[0] / 14;
    int e = in_sizes[13] / 2;
    int s = in_sizes[14];

    float* out = (float*)d_out;
    size_t NH = (size_t)n * 105;
    float* outB = out;
    float* outS = out + NH;
    float* selB = out + 2 * NH;
    float* selS = out + 3 * NH;

    int prep_threads = max(s, (e + 1) / 2);
    int scat_threads = max(e, n * 16);

    k_init    <<<(n + 255) / 256, 256>>>((const int*)ei, n);
    k_prep    <<<(prep_threads + 255) / 256, 256>>>(ei, si, e, s);
    k_chunksum<<<128, 256>>>(n);
    k_offsets <<<128, 256>>>(n, e);
    k_scatter <<<(scat_threads + 255) / 256, 256>>>(ei, x, e, n);
    k_agg16   <<<(n + 7) / 8, 256>>>(W1, b1, dr1, n);
    k_agg64   <<<(n + 7) / 8, 256>>>(n);
    k_gemm64  <<<(n + 63) / 64, 64>>>(W2, b2, dr2, n);
    k_heads   <<<dim3((n + 63) / 64, 2), 128>>>(Wb, bb, Ws, bs, gb, gs,
                                                outB, outS, selB, selS, n);
}

// round 15
// speedup vs baseline: 1.1033x; 1.1033x over previous
#include <cuda_runtime.h>

// ---------------------------------------------------------------------------
// ActorGCN: 2-layer GCN + two 105-way heads + gumbel softmax
// N=100000 nodes, E=1600000 edges, H=64, F_IN=14, heads 105+105
// Layer 1 uses (A@X)@W1; the 15x64 transform is fused into agg16's epilogue.
// RULES learned: (1) no global-loops in grid-1 kernels (issue throttle);
// (2) gumbel-softmax stays a separate coalesced warp-per-row kernel
//     (three fusion attempts all regressed ~+35us).
// ---------------------------------------------------------------------------

#define NN 100000
#define EE 1600000

typedef unsigned long long ull;

__device__ __forceinline__ ull pk2(float lo, float hi) {
    ull r; asm("mov.b64 %0, {%1, %2};" : "=l"(r) : "f"(lo), "f"(hi)); return r;
}
__device__ __forceinline__ void upk2(ull v, float& lo, float& hi) {
    asm("mov.b64 {%0, %1}, %2;" : "=f"(lo), "=f"(hi) : "l"(v));
}
__device__ __forceinline__ ull fma2(ull a, ull b, ull c) {
    ull d; asm("fma.rn.f32x2 %0, %1, %2, %3;" : "=l"(d) : "l"(a), "l"(b), "l"(c)); return d;
}

__device__ float g_bufA[NN * 64];
__device__ float g_bufB[NN * 64];
__device__ float g_x16[NN * 16];
__device__ int   g_ecnt[NN];
__device__ float g_dinv[NN];
__device__ float g_stem[NN];
__device__ int   g_off[NN + 1];
__device__ int   g_cur[NN];
__device__ int2  g_edge[EE];      // .x = src, .y = float bits of dinv[src]
__device__ int   g_csum[1024];
__device__ int   g_is64;

__device__ __forceinline__ int idx_at(const void* p, long long i) {
    return g_is64 ? (int)((const long long*)p)[i] : ((const int*)p)[i];
}

// init counters/stem; block 0 also probes index dtype (int64 vs int32).
__global__ void k_init(const int* __restrict__ ei32, int n) {
    int i = blockIdx.x * blockDim.x + threadIdx.x;
    if (i < n) { g_ecnt[i] = 0; g_stem[i] = 0.f; }
    if (blockIdx.x == 0) {
        __shared__ int nonzero;
        if (threadIdx.x == 0) nonzero = 0;
        __syncthreads();
        for (int k = threadIdx.x; k < 1024; k += blockDim.x) {
            if (ei32[2 * k + 1] != 0) nonzero = 1;
        }
        __syncthreads();
        if (threadIdx.x == 0) g_is64 = nonzero ? 0 : 1;
    }
}

// Fused: stem scatter (i < s) + dst histogram (2 edges per thread).
__global__ void k_prep(const void* __restrict__ ei, const void* __restrict__ si,
                       int e, int s) {
    int i = blockIdx.x * blockDim.x + threadIdx.x;
    if (i < s) {
        int v = idx_at(si, i);
        if (v >= 0 && v < NN) g_stem[v] = 1.0f;
    }
    int j = i * 2;
    if (j < e) {
        if (g_is64) {
            const long long* dst = (const long long*)ei + e;
            int d0 = (int)dst[j];
            if (d0 >= 0 && d0 < NN) atomicAdd(&g_ecnt[d0], 1);
            if (j + 1 < e) {
                int d1 = (int)dst[j + 1];
                if (d1 >= 0 && d1 < NN) atomicAdd(&g_ecnt[d1], 1);
            }
        } else {
            const int* dst = (const int*)ei + e;
            int d0 = dst[j];
            if (d0 >= 0 && d0 < NN) atomicAdd(&g_ecnt[d0], 1);
            if (j + 1 < e) {
                int d1 = dst[j + 1];
                if (d1 >= 0 && d1 < NN) atomicAdd(&g_ecnt[d1], 1);
            }
        }
    }
}

// Warp-per-chunk sums: 1024 chunks, coalesced loads + shfl reduce.
__global__ void k_chunksum(int n) {
    int c = blockIdx.x * 8 + (threadIdx.x >> 5);
    int lane = threadIdx.x & 31;
    int ch = (n + 1023) >> 10;
    int beg = min(n, c * ch), end = min(n, beg + ch);
    int sum = 0;
    for (int i = beg + lane; i < end; i += 32) sum += g_ecnt[i];
    #pragma unroll
    for (int off = 16; off; off >>= 1) sum += __shfl_xor_sync(0xffffffffu, sum, off);
    if (lane == 0) g_csum[c] = sum;
}

// Warp-per-chunk offsets. Each CTA redundantly scans the 1024 chunk sums in
// smem (replaces the dedicated grid-1 scan kernel), then writes its 8 chunks.
__global__ void k_offsets(int n, int e) {
    __shared__ int sh[1024];
    __shared__ int sh2[256];
    int tid = threadIdx.x;        // 256 threads
    int v0 = g_csum[tid * 4], v1 = g_csum[tid * 4 + 1];
    int v2 = g_csum[tid * 4 + 2], v3 = g_csum[tid * 4 + 3];
    int l1 = v0 + v1, l2 = l1 + v2, l3 = l2 + v3;
    sh2[tid] = l3;
    __syncthreads();
    for (int off = 1; off < 256; off <<= 1) {
        int add = (tid >= off) ? sh2[tid - off] : 0;
        __syncthreads();
        sh2[tid] += add;
        __syncthreads();
    }
    int pre = sh2[tid] - l3;
    sh[tid * 4]     = pre;
    sh[tid * 4 + 1] = pre + v0;
    sh[tid * 4 + 2] = pre + l1;
    sh[tid * 4 + 3] = pre + l2;
    __syncthreads();

    int c = blockIdx.x * 8 + (tid >> 5);
    int lane = tid & 31;
    int ch = (n + 1023) >> 10;
    int beg = min(n, c * ch), end = min(n, beg + ch);
    int run = sh[c];
    for (int base = beg; base < end; base += 32) {
        int i = base + lane;
        int d = (i < end) ? g_ecnt[i] : 0;
        int incl = d;
        #pragma unroll
        for (int off = 1; off < 32; off <<= 1) {
            int v = __shfl_up_sync(0xffffffffu, incl, off);
            if (lane >= off) incl += v;
        }
        if (i < end) {
            int o = run + incl - d;
            g_off[i] = o;
            g_cur[i] = o;
            g_dinv[i] = rsqrtf((float)(d + 1));   // +1 self-loop
        }
        run += __shfl_sync(0xffffffffu, incl, 31);
    }
    if (blockIdx.x == 0 && threadIdx.x == 0) g_off[n] = e;
}

// Fused: CSR scatter (2 edges/thread, vectorized int64 loads) +
// pack [x|stem|0] into padded 16-float rows (1 element/thread).
__global__ void k_scatter(const void* __restrict__ ei, const float* __restrict__ x,
                          int e, int n) {
    int i = blockIdx.x * blockDim.x + threadIdx.x;
    int j = i * 2;
    if (j < e) {
        int s0, d0, s1 = -1, d1 = -1;
        bool two = (j + 1 < e);
        if (g_is64) {
            const long long* src = (const long long*)ei;
            const long long* dst = src + e;
            if (two && ((((unsigned long long)(src + j)) & 15) == 0) &&
                       ((((unsigned long long)(dst + j)) & 15) == 0)) {
                longlong2 sv = *(const longlong2*)(src + j);
                longlong2 dv = *(const longlong2*)(dst + j);
                s0 = (int)sv.x; s1 = (int)sv.y;
                d0 = (int)dv.x; d1 = (int)dv.y;
            } else {
                s0 = (int)src[j]; d0 = (int)dst[j];
                if (two) { s1 = (int)src[j + 1]; d1 = (int)dst[j + 1]; }
            }
        } else {
            const int* src = (const int*)ei;
            const int* dst = src + e;
            s0 = src[j]; d0 = dst[j];
            if (two) { s1 = src[j + 1]; d1 = dst[j + 1]; }
        }
        if (s0 >= 0 && s0 < NN && d0 >= 0 && d0 < NN) {
            int p = atomicAdd(&g_cur[d0], 1);
            if (p >= 0 && p < EE)
                g_edge[p] = make_int2(s0, __float_as_int(g_dinv[s0]));
        }
        if (two && s1 >= 0 && s1 < NN && d1 >= 0 && d1 < NN) {
            int p = atomicAdd(&g_cur[d1], 1);
            if (p >= 0 && p < EE)
                g_edge[p] = make_int2(s1, __float_as_int(g_dinv[s1]));
        }
    }
    if (i < n * 16) {
        int node = i >> 4, f = i & 15;
        float v = 0.f;
        if (f < 14)       v = x[node * 14 + f];
        else if (f == 14) v = g_stem[node];
        g_x16[i] = v;
    }
}

// Fused layer 1: aggregate 16-feat raw input, then 15x64 transform + bias +
// relu + drop, all in one warp per node. Writes h1 -> g_bufB.
__global__ void k_agg16(const float* __restrict__ W1, const float* __restrict__ b1,
                        const float* __restrict__ drop, int n) {
    __shared__ float sW[15 * 64];
    __shared__ int   s_idx[8][32];
    __shared__ float s_w[8][32];
    int wrp = threadIdx.x >> 5, lane = threadIdx.x & 31;
    for (int idx = threadIdx.x; idx < 15 * 64; idx += 256) sW[idx] = W1[idx];
    __syncthreads();
    int node = blockIdx.x * 8 + wrp;
    if (node >= n) return;
    int f = lane & 15, half = lane >> 4;
    const float* __restrict__ in = g_x16;
    float di = g_dinv[node];
    float acc = half ? 0.f : di * in[node * 16 + f];
    int beg = g_off[node], end = g_off[node + 1];
    for (int base = beg; base < end; base += 32) {
        int m = min(32, end - base);
        if (lane < m) {
            int2 v = g_edge[base + lane];
            s_idx[wrp][lane] = v.x;
            s_w[wrp][lane]   = __int_as_float(v.y);
        }
        __syncwarp();
        int j = 0;
        for (; j + 8 <= m; j += 8) {
            int e0 = j + half, e1 = j + 2 + half, e2 = j + 4 + half, e3 = j + 6 + half;
            float v0 = in[s_idx[wrp][e0] * 16 + f];
            float v1 = in[s_idx[wrp][e1] * 16 + f];
            float v2 = in[s_idx[wrp][e2] * 16 + f];
            float v3 = in[s_idx[wrp][e3] * 16 + f];
            acc = fmaf(s_w[wrp][e0], v0, acc);
            acc = fmaf(s_w[wrp][e1], v1, acc);
            acc = fmaf(s_w[wrp][e2], v2, acc);
            acc = fmaf(s_w[wrp][e3], v3, acc);
        }
        for (; j < m; j += 2) {
            int e2 = j + half;
            if (e2 < m)
                acc = fmaf(s_w[wrp][e2], in[s_idx[wrp][e2] * 16 + f], acc);
        }
        __syncwarp();
    }
    acc += __shfl_xor_sync(0xffffffffu, acc, 16);   // all lanes: a16[lane&15] sum
    float a16v = di * acc;
    float h0 = b1[lane], h1 = b1[lane + 32];
    #pragma unroll
    for (int k = 0; k < 15; k++) {
        float ak = __shfl_sync(0xffffffffu, a16v, k);
        h0 = fmaf(ak, sW[k * 64 + lane], h0);
        h1 = fmaf(ak, sW[k * 64 + lane + 32], h1);
    }
    h0 = fmaxf(h0, 0.f) * drop[(size_t)node * 64 + lane];
    h1 = fmaxf(h1, 0.f) * drop[(size_t)node * 64 + lane + 32];
    g_bufB[node * 64 + lane] = h0;
    g_bufB[node * 64 + lane + 32] = h1;
}

// Pure aggregation of h1 (64 feats): bufA[i] = dinv_i*(dinv_i*h1[i] + sum w*h1[src]).
__global__ void k_agg64(int n) {
    __shared__ int   s_idx[8][32];
    __shared__ float s_w[8][32];
    int wrp = threadIdx.x >> 5, lane = threadIdx.x & 31;
    int node = blockIdx.x * 8 + wrp;
    if (node >= n) return;
    const ull* __restrict__ in2 = (const ull*)g_bufB;
    float di = g_dinv[node];
    float sx, sy;
    upk2(in2[node * 32 + lane], sx, sy);
    ull acc = pk2(di * sx, di * sy);
    int beg = g_off[node], end = g_off[node + 1];
    for (int base = beg; base < end; base += 32) {
        int m = min(32, end - base);
        if (lane < m) {
            int2 v = g_edge[base + lane];
            s_idx[wrp][lane] = v.x;
            s_w[wrp][lane]   = __int_as_float(v.y);
        }
        __syncwarp();
        int j = 0;
        for (; j + 8 <= m; j += 8) {
            ull v0 = in2[s_idx[wrp][j    ] * 32 + lane];
            ull v1 = in2[s_idx[wrp][j + 1] * 32 + lane];
            ull v2 = in2[s_idx[wrp][j + 2] * 32 + lane];
            ull v3 = in2[s_idx[wrp][j + 3] * 32 + lane];
            ull v4 = in2[s_idx[wrp][j + 4] * 32 + lane];
            ull v5 = in2[s_idx[wrp][j + 5] * 32 + lane];
            ull v6 = in2[s_idx[wrp][j + 6] * 32 + lane];
            ull v7 = in2[s_idx[wrp][j + 7] * 32 + lane];
            acc = fma2(v0, pk2(s_w[wrp][j    ], s_w[wrp][j    ]), acc);
            acc = fma2(v1, pk2(s_w[wrp][j + 1], s_w[wrp][j + 1]), acc);
            acc = fma2(v2, pk2(s_w[wrp][j + 2], s_w[wrp][j + 2]), acc);
            acc = fma2(v3, pk2(s_w[wrp][j + 3], s_w[wrp][j + 3]), acc);
            acc = fma2(v4, pk2(s_w[wrp][j + 4], s_w[wrp][j + 4]), acc);
            acc = fma2(v5, pk2(s_w[wrp][j + 5], s_w[wrp][j + 5]), acc);
            acc = fma2(v6, pk2(s_w[wrp][j + 6], s_w[wrp][j + 6]), acc);
            acc = fma2(v7, pk2(s_w[wrp][j + 7], s_w[wrp][j + 7]), acc);
        }
        for (; j < m; j++) {
            ull v = in2[s_idx[wrp][j] * 32 + lane];
            float w = s_w[wrp][j];
            acc = fma2(v, pk2(w, w), acc);
        }
        __syncwarp();
    }
    float ax, ay;
    upk2(acc, ax, ay);
    ((float2*)g_bufA)[node * 32 + lane] = make_float2(di * ax, di * ay);
}

// h2 = relu(bufA @ W2 + b2) * drop2 -> bufB. 64 threads, BM=64, 8x8, f32x2.
__global__ void k_gemm64(const float* __restrict__ W, const float* __restrict__ b2,
                         const float* __restrict__ drop, int n) {
    __shared__ float Ash[64 * 65];
    __shared__ float Wsh[64 * 64];
    __shared__ float bsh[64];
    int tid = threadIdx.x;        // 64 threads
    int base = blockIdx.x * 64;
    for (int idx = tid; idx < 4096; idx += 64) Wsh[idx] = W[idx];
    bsh[tid] = b2[tid];
    for (int idx = tid; idx < 4096; idx += 64) {
        int nl = idx >> 6, k = idx & 63;
        int node = base + nl;
        Ash[nl * 65 + k] = (node < n) ? g_bufA[node * 64 + k] : 0.f;
    }
    __syncthreads();
    int tx = tid & 7, ty = tid >> 3;
    ull acc[8][4];
    #pragma unroll
    for (int r = 0; r < 8; r++)
        #pragma unroll
        for (int c = 0; c < 4; c++) acc[r][c] = 0ull;
    #pragma unroll 4
    for (int k = 0; k < 64; k++) {
        const ull* wrow = (const ull*)&Wsh[k * 64 + tx * 8];
        ull w0 = wrow[0], w1 = wrow[1], w2 = wrow[2], w3 = wrow[3];
        #pragma unroll
        for (int r = 0; r < 8; r++) {
            float a = Ash[(ty * 8 + r) * 65 + k];
            ull a2 = pk2(a, a);
            acc[r][0] = fma2(a2, w0, acc[r][0]);
            acc[r][1] = fma2(a2, w1, acc[r][1]);
            acc[r][2] = fma2(a2, w2, acc[r][2]);
            acc[r][3] = fma2(a2, w3, acc[r][3]);
        }
    }
    #pragma unroll
    for (int r = 0; r < 8; r++) {
        int node = base + ty * 8 + r;
        if (node < n) {
            #pragma unroll
            for (int c2 = 0; c2 < 4; c2++) {
                float p0, p1;
                upk2(acc[r][c2], p0, p1);
                int col0 = tx * 8 + c2 * 2;
                float2 dv = ((const float2*)drop)[(size_t)node * 32 + tx * 4 + c2];
                float o0 = fmaxf(p0 + bsh[col0], 0.f) * dv.x;
                float o1 = fmaxf(p1 + bsh[col0 + 1], 0.f) * dv.y;
                ((float2*)g_bufB)[node * 32 + tx * 4 + c2] = make_float2(o0, o1);
            }
        }
    }
}

// Heads GEMM: BM=64 nodes x BN=112 cols, one head per blockIdx.y.
// 112 threads: tx=0..13 (8 cols), ty=0..7 (8 rows). f32x2 accumulate.
__global__ void k_heads(const float* __restrict__ Wb, const float* __restrict__ bbv,
                        const float* __restrict__ Wst, const float* __restrict__ bsv,
                        float* __restrict__ outB, float* __restrict__ outS, int n) {
    __shared__ float Ash[64 * 65];
    __shared__ float Wsh[64 * 112];
    __shared__ float bias_s[112];
    int tid = threadIdx.x;        // 112 threads
    int base = blockIdx.x * 64;
    const float* __restrict__ W  = blockIdx.y ? Wst : Wb;
    const float* __restrict__ bv = blockIdx.y ? bsv : bbv;
    float* __restrict__ out      = blockIdx.y ? outS : outB;

    bias_s[tid] = (tid < 105) ? bv[tid] : 0.f;
    {
        int col = tid;
        for (int k = 0; k < 64; k++)
            Wsh[k * 112 + col] = (col < 105) ? W[k * 105 + col] : 0.f;
    }
    for (int idx = tid; idx < 4096; idx += 112) {
        int nl = idx >> 6, k = idx & 63;
        int node = base + nl;
        Ash[nl * 65 + k] = (node < n) ? g_bufB[node * 64 + k] : 0.f;
    }
    __syncthreads();
    int tx = tid % 14, ty = tid / 14;
    ull acc[8][4];
    #pragma unroll
    for (int r = 0; r < 8; r++)
        #pragma unroll
        for (int c = 0; c < 4; c++) acc[r][c] = 0ull;
    #pragma unroll 2
    for (int k = 0; k < 64; k++) {
        const ull* wrow = (const ull*)&Wsh[k * 112 + tx * 8];
        ull w0 = wrow[0], w1 = wrow[1], w2 = wrow[2], w3 = wrow[3];
        #pragma unroll
        for (int r = 0; r < 8; r++) {
            float a = Ash[(ty * 8 + r) * 65 + k];
            ull a2 = pk2(a, a);
            acc[r][0] = fma2(a2, w0, acc[r][0]);
            acc[r][1] = fma2(a2, w1, acc[r][1]);
            acc[r][2] = fma2(a2, w2, acc[r][2]);
            acc[r][3] = fma2(a2, w3, acc[r][3]);
        }
    }
    #pragma unroll
    for (int r = 0; r < 8; r++) {
        int node = base + ty * 8 + r;
        if (node < n) {
            #pragma unroll
            for (int c2 = 0; c2 < 4; c2++) {
                float p0, p1;
                upk2(acc[r][c2], p0, p1);
                int col0 = tx * 8 + c2 * 2;
                int col1 = col0 + 1;
                if (col0 < 105) out[(size_t)node * 105 + col0] = p0 + bias_s[col0];
                if (col1 < 105) out[(size_t)node * 105 + col1] = p1 + bias_s[col1];
            }
        }
    }
}

// Warp-per-row softmax over 105 entries of (logits + gumbel); 2n rows.
__global__ void k_softmax2(const float* __restrict__ LB, const float* __restrict__ GB,
                           float* __restrict__ OB,
                           const float* __restrict__ LS, const float* __restrict__ GS,
                           float* __restrict__ OS, int n) {
    int w = blockIdx.x * 8 + (threadIdx.x >> 5);
    if (w >= 2 * n) return;
    int lane = threadIdx.x & 31;
    int row = (w < n) ? w : (w - n);
    const float* L = (w < n) ? LB : LS;
    const float* G = (w < n) ? GB : GS;
    float*       O = (w < n) ? OB : OS;
    size_t o = (size_t)row * 105;
    float v0 = L[o + lane]      + G[o + lane];
    float v1 = L[o + lane + 32] + G[o + lane + 32];
    float v2 = L[o + lane + 64] + G[o + lane + 64];
    float v3 = (lane < 9) ? (L[o + lane + 96] + G[o + lane + 96]) : -1e30f;
    float m = fmaxf(fmaxf(v0, v1), fmaxf(v2, v3));
    #pragma unroll
    for (int off = 16; off; off >>= 1) m = fmaxf(m, __shfl_xor_sync(0xffffffffu, m, off));
    float e0 = __expf(v0 - m), e1 = __expf(v1 - m), e2 = __expf(v2 - m);
    float e3 = (lane < 9) ? __expf(v3 - m) : 0.f;
    float s = e0 + e1 + e2 + e3;
    #pragma unroll
    for (int off = 16; off; off >>= 1) s += __shfl_xor_sync(0xffffffffu, s, off);
    float inv = 1.0f / s;
    O[o + lane]      = e0 * inv;
    O[o + lane + 32] = e1 * inv;
    O[o + lane + 64] = e2 * inv;
    if (lane < 9) O[o + lane + 96] = e3 * inv;
}

extern "C" void kernel_launch(void* const* d_in, const int* in_sizes, int n_in,
                              void* d_out, int out_size) {
    const float* x   = (const float*)d_in[0];
    const float* W1  = (const float*)d_in[1];
    const float* b1  = (const float*)d_in[2];
    const float* W2  = (const float*)d_in[3];
    const float* b2  = (const float*)d_in[4];
    const float* Wb  = (const float*)d_in[5];
    const float* bb  = (const float*)d_in[6];
    const float* Ws  = (const float*)d_in[7];
    const float* bs  = (const float*)d_in[8];
    const float* dr1 = (const float*)d_in[9];
    const float* dr2 = (const float*)d_in[10];
    const float* gb  = (const float*)d_in[11];
    const float* gs  = (const float*)d_in[12];
    const void*  ei  = d_in[13];
    const void*  si  = d_in[14];

    int n = in_sizes[0] / 14;
    int e = in_sizes[13] / 2;
    int s = in_sizes[14];

    float* out = (float*)d_out;
    size_t NH = (size_t)n * 105;
    float* outB = out;
    float* outS = out + NH;
    float* selB = out + 2 * NH;
    float* selS = out + 3 * NH;

    int prep_threads = max(s, (e + 1) / 2);
    int scat_threads = max((e + 1) / 2, n * 16);

    k_init    <<<(n + 255) / 256, 256>>>((const int*)ei, n);
    k_prep    <<<(prep_threads + 255) / 256, 256>>>(ei, si, e, s);
    k_chunksum<<<128, 256>>>(n);
    k_offsets <<<128, 256>>>(n, e);
    k_scatter <<<(scat_threads + 255) / 256, 256>>>(ei, x, e, n);
    k_agg16   <<<(n + 7) / 8, 256>>>(W1, b1, dr1, n);
    k_agg64   <<<(n + 7) / 8, 256>>>(n);
    k_gemm64  <<<(n + 63) / 64, 64>>>(W2, b2, dr2, n);
    k_heads   <<<dim3((n + 63) / 64, 2), 112>>>(Wb, bb, Ws, bs, outB, outS, n);
    k_softmax2<<<(2 * n + 7) / 8, 256>>>(outB, gb, selB, outS, gs, selS, n);
}